// round 16
// baseline (speedup 1.0000x reference)
#include <cuda_runtime.h>
#include <cuda_fp16.h>
#include <math.h>
#include <stdint.h>

#define BB 4
#define SS 2048
#define EE 512
#define HH 8
#define DD 64

#define STRH 72                 // flash SMEM tile row stride in halves
#define TILEH (64 * STRH)       // halves per 64x64 tile (pad cols 64..71)
#define STAGEH (2 * TILEH)      // K tile + V tile per pipeline stage
#define FSMEM (3 * STAGEH * (int)sizeof(__half))   // 55296 B

// softmax scale folded into Q: 1/sqrt(512) * log2(e)
#define CS 0.06376686479f

// Scratch (allocation-free requirement -> __device__ globals)
__device__ __half g_qh[BB * HH * SS * DD];  // [B,H,S,D] fp16, pre-scaled by CS
__device__ __half g_kh[BB * HH * SS * DD];  // [B,H,S,D] fp16
__device__ __half g_vh[BB * HH * SS * DD];  // [B,H,S,D] fp16
__device__ __half g_oh[BB * SS * EE];       // attention output [B,S,E] fp16
__device__ __half g_woh[EE * EE];           // Wo in fp16

// ---------------------------------------------------------------------------
// helpers
// ---------------------------------------------------------------------------
__device__ __forceinline__ uint32_t packh2(float lo, float hi) {
    uint32_t d;
    asm("cvt.rn.f16x2.f32 %0, %1, %2;" : "=r"(d) : "f"(hi), "f"(lo));
    return d;
}

__device__ __forceinline__ uint32_t ex2h2(uint32_t a) {
    uint32_t d;
    asm("ex2.approx.f16x2 %0, %1;" : "=r"(d) : "r"(a));
    return d;
}

__device__ __forceinline__ void mma_f16(float d[4], const uint32_t a[4],
                                        uint32_t b0, uint32_t b1) {
    asm volatile(
        "mma.sync.aligned.m16n8k16.row.col.f32.f16.f16.f32 "
        "{%0,%1,%2,%3}, {%4,%5,%6,%7}, {%8,%9}, {%0,%1,%2,%3};"
        : "+f"(d[0]), "+f"(d[1]), "+f"(d[2]), "+f"(d[3])
        : "r"(a[0]), "r"(a[1]), "r"(a[2]), "r"(a[3]), "r"(b0), "r"(b1));
}

// fp16-accumulate variant: D/C are 2 packed f16x2 regs (2x HMMA rate)
__device__ __forceinline__ void mma_f16h(uint32_t d[2], const uint32_t a[4],
                                         uint32_t b0, uint32_t b1) {
    asm volatile(
        "mma.sync.aligned.m16n8k16.row.col.f16.f16.f16.f16 "
        "{%0,%1}, {%2,%3,%4,%5}, {%6,%7}, {%0,%1};"
        : "+r"(d[0]), "+r"(d[1])
        : "r"(a[0]), "r"(a[1]), "r"(a[2]), "r"(a[3]), "r"(b0), "r"(b1));
}

__device__ __forceinline__ void ldsm4(uint32_t r[4], const __half* p) {
    uint32_t a = (uint32_t)__cvta_generic_to_shared(p);
    asm volatile("ldmatrix.sync.aligned.m8n8.x4.shared.b16 {%0,%1,%2,%3}, [%4];"
                 : "=r"(r[0]), "=r"(r[1]), "=r"(r[2]), "=r"(r[3]) : "r"(a));
}

__device__ __forceinline__ void ldsm4t(uint32_t r[4], const __half* p) {
    uint32_t a = (uint32_t)__cvta_generic_to_shared(p);
    asm volatile("ldmatrix.sync.aligned.m8n8.x4.trans.shared.b16 {%0,%1,%2,%3}, [%4];"
                 : "=r"(r[0]), "=r"(r[1]), "=r"(r[2]), "=r"(r[3]) : "r"(a));
}

__device__ __forceinline__ void ldsm2t(uint32_t r[2], const __half* p) {
    uint32_t a = (uint32_t)__cvta_generic_to_shared(p);
    asm volatile("ldmatrix.sync.aligned.m8n8.x2.trans.shared.b16 {%0,%1}, [%2];"
                 : "=r"(r[0]), "=r"(r[1]) : "r"(a));
}

__device__ __forceinline__ void cp16h(__half* smem_dst, const __half* gsrc) {
    uint32_t s = (uint32_t)__cvta_generic_to_shared(smem_dst);
    asm volatile("cp.async.cg.shared.global [%0], [%1], 16;" :: "r"(s), "l"(gsrc));
}

// ---------------------------------------------------------------------------
// Kernel 1: fused per-head projections on fp16 tensor cores + Wo convert.
// grid (512, 4); blockIdx.y: 0=Q, 1=K, 2=V, 3=Wo fp32->fp16.
// ---------------------------------------------------------------------------
#define PXSTR 72

__global__ void __launch_bounds__(256) proj_mma(
    const float* __restrict__ q, const float* __restrict__ k,
    const float* __restrict__ v,
    const float* __restrict__ Wq, const float* __restrict__ Wk,
    const float* __restrict__ Wv, const float* __restrict__ Wo)
{
    int which = blockIdx.y;
    if (which == 3) {
        int i = (blockIdx.x * 256 + threadIdx.x) * 2;
        float2 f = *(const float2*)(Wo + i);
        *(uint32_t*)(g_woh + i) = packh2(f.x, f.y);
        return;
    }

    const float* x = (which == 0) ? q : (which == 1) ? k : v;
    const float* W = (which == 0) ? Wq : (which == 1) ? Wk : Wv;
    __half* outh   = (which == 0) ? g_qh : (which == 1) ? g_kh : g_vh;
    float scale    = (which == 0) ? CS : 1.0f;

    __shared__ __half Xs[128 * PXSTR];   // also reused as epilogue buffer
    __shared__ __half Ws[64 * PXSTR];

    int t  = threadIdx.x;
    int l  = t & 31;
    int w  = t >> 5;
    int r  = l >> 2;
    int c  = l & 3;
    int m  = l >> 3;
    int lm = l & 7;
    int arow = (m & 1) * 8 + lm, acol = (m >> 1) * 8;
    int brow = (m >> 1) * 8 + lm, bcol = (m & 1) * 8;

    int rbase = blockIdx.x * 128;

    {
        int row = t >> 2, c16 = (t & 3) * 16;
        const float* wp = W + row * 64 + c16;
        float4 f0 = *(const float4*)(wp);
        float4 f1 = *(const float4*)(wp + 4);
        float4 f2 = *(const float4*)(wp + 8);
        float4 f3 = *(const float4*)(wp + 12);
        uint4 u0, u1;
        u0.x = packh2(f0.x, f0.y); u0.y = packh2(f0.z, f0.w);
        u0.z = packh2(f1.x, f1.y); u0.w = packh2(f1.z, f1.w);
        u1.x = packh2(f2.x, f2.y); u1.y = packh2(f2.z, f2.w);
        u1.z = packh2(f3.x, f3.y); u1.w = packh2(f3.z, f3.w);
        *(uint4*)(&Ws[row * PXSTR + c16])     = u0;
        *(uint4*)(&Ws[row * PXSTR + c16 + 8]) = u1;
    }
    {
#pragma unroll
        for (int i = 0; i < 2; i++) {
            int idx = t + 256 * i;
            int row = idx >> 2, c16 = (idx & 3) * 16;
            const float* xp = x + (size_t)(rbase + row) * 64 + c16;
            float4 f0 = *(const float4*)(xp);
            float4 f1 = *(const float4*)(xp + 4);
            float4 f2 = *(const float4*)(xp + 8);
            float4 f3 = *(const float4*)(xp + 12);
            uint4 u0, u1;
            u0.x = packh2(f0.x, f0.y); u0.y = packh2(f0.z, f0.w);
            u0.z = packh2(f1.x, f1.y); u0.w = packh2(f1.z, f1.w);
            u1.x = packh2(f2.x, f2.y); u1.y = packh2(f2.z, f2.w);
            u1.z = packh2(f3.x, f3.y); u1.w = packh2(f3.z, f3.w);
            *(uint4*)(&Xs[row * PXSTR + c16])     = u0;
            *(uint4*)(&Xs[row * PXSTR + c16 + 8]) = u1;
        }
    }
    __syncthreads();

    float acc[8][4];
#pragma unroll
    for (int nb = 0; nb < 8; nb++)
#pragma unroll
        for (int j = 0; j < 4; j++) acc[nb][j] = 0.f;

#pragma unroll
    for (int k16 = 0; k16 < 4; k16++) {
        int kk = k16 * 16;
        uint32_t af[4];
        ldsm4(af, &Xs[(w * 16 + arow) * PXSTR + kk + acol]);
#pragma unroll
        for (int nb2 = 0; nb2 < 4; nb2++) {
            uint32_t bf[4];
            ldsm4(bf, &Ws[(nb2 * 16 + brow) * PXSTR + kk + bcol]);
            mma_f16(acc[2 * nb2    ], af, bf[0], bf[1]);
            mma_f16(acc[2 * nb2 + 1], af, bf[2], bf[3]);
        }
    }

    __syncthreads();
    __half* Es = Xs;
#pragma unroll
    for (int half = 0; half < 2; half++) {
        int row = w * 16 + r + 8 * half;
#pragma unroll
        for (int nb = 0; nb < 8; nb++) {
            *(uint32_t*)(&Es[row * PXSTR + nb * 8 + 2 * c]) =
                packh2(acc[nb][2 * half] * scale, acc[nb][2 * half + 1] * scale);
        }
    }
    __syncthreads();

#pragma unroll
    for (int i = t; i < 1024; i += 256) {
        int row = i >> 3, seg = i & 7;
        int n   = rbase + row;
        int b   = n >> 14;
        int rem = n & 16383;
        int s   = rem >> 3;
        int h   = rem & 7;
        __half* Ob = outh + (((size_t)(b * HH + h) * SS) + s) * 64;
        *(uint4*)(Ob + seg * 8) = *(const uint4*)(&Es[row * PXSTR + seg * 8]);
    }
}

// ---------------------------------------------------------------------------
// Kernel 2: flash attention, flash9 structure + in-place ex2 (pa array
// eliminated, ~32 fewer regs) + 3 CTAs/SM (512 CTAs / 444 slots = 1.15 waves).
// fp16-acc GEMM1, fp32-acc GEMM2, ones-column row sums, warp M-tile 32,
// 4 warps/CTA, q-block 128, Bc = 64, 3-stage cp.async ring, 1 barrier/tile.
// ---------------------------------------------------------------------------
__global__ void __launch_bounds__(128, 3) flash11_kernel()
{
    extern __shared__ __half hsm[];   // 3 stages x (K tile + V tile)

    int t  = threadIdx.x;
    int l  = t & 31;
    int w  = t >> 5;                // 0..3, warp owns rows w*32..w*32+31
    int bh = blockIdx.y;
    int q0 = blockIdx.x * 128;
    int r  = l >> 2;
    int c  = l & 3;
    int m  = l >> 3;
    int lm = l & 7;

    int krow = (m >> 1) * 8 + lm;   // K ldsm (non-trans)
    int kcol = (m & 1) * 8;
    int vrow = (m & 1) * 8 + lm;    // V ldsm (trans)
    int vcol = (m >> 1) * 8;
    int lm2  = l & 7;               // ldsm2t lanes
    int mb   = (l >> 3) & 1;

    const __half* Kg = g_kh + (size_t)bh * SS * DD;
    const __half* Vg = g_vh + (size_t)bh * SS * DD;

    // ---- V pad columns: [1,0,...,0] per row, all 3 stages (written once) ----
    for (int i = t; i < 192; i += 128) {
        int stg = i >> 6, row = i & 63;
        uint4 z; z.x = 0x00003C00u; z.y = 0; z.z = 0; z.w = 0;
        *(uint4*)(hsm + stg * STAGEH + TILEH + row * STRH + 64) = z;
    }

    // ---- Q a-fragments: 2 m16 sub-tiles (rows w*32 and w*32+16) ----
    uint32_t qf[2][4][4];
    {
        const __half* Qb = g_qh + ((size_t)bh * SS + q0 + w * 32) * DD;
#pragma unroll
        for (int mi = 0; mi < 2; mi++)
#pragma unroll
            for (int kb = 0; kb < 4; kb++) {
                const __half* Qm = Qb + (size_t)mi * 16 * 64;
                qf[mi][kb][0] = *(const uint32_t*)(Qm + (r    ) * 64 + kb * 16 + 2 * c    );
                qf[mi][kb][1] = *(const uint32_t*)(Qm + (r + 8) * 64 + kb * 16 + 2 * c    );
                qf[mi][kb][2] = *(const uint32_t*)(Qm + (r    ) * 64 + kb * 16 + 2 * c + 8);
                qf[mi][kb][3] = *(const uint32_t*)(Qm + (r + 8) * 64 + kb * 16 + 2 * c + 8);
            }
    }

    float o[2][8][4];
#pragma unroll
    for (int mi = 0; mi < 2; mi++)
#pragma unroll
        for (int nb = 0; nb < 8; nb++)
#pragma unroll
            for (int j = 0; j < 4; j++) o[mi][nb][j] = 0.f;
    float osum[2][4] = {{0.f, 0.f, 0.f, 0.f}, {0.f, 0.f, 0.f, 0.f}};

    // prologue: load tiles 0 and 1 into stages 0 and 1
#pragma unroll
    for (int pt = 0; pt < 2; pt++) {
        __half* Kd = hsm + pt * STAGEH;
        __half* Vd = Kd + TILEH;
        const __half* Kgs = Kg + (size_t)pt * 64 * DD;
        const __half* Vgs = Vg + (size_t)pt * 64 * DD;
#pragma unroll
        for (int i = 0; i < 4; i++) {
            int idx = t + 128 * i;          // 0..511
            int row = idx >> 3, c8 = (idx & 7) * 8;
            cp16h(&Kd[row * STRH + c8], Kgs + row * DD + c8);
            cp16h(&Vd[row * STRH + c8], Vgs + row * DD + c8);
        }
        asm volatile("cp.async.commit_group;");
    }

    int stg = 0;                  // stage of tile kt
    int pstg = 2;                 // stage receiving tile kt+2

    for (int kt = 0; kt < SS / 64; kt++) {
        if (kt == SS / 64 - 1) {
            asm volatile("cp.async.wait_group 0;");
        } else {
            asm volatile("cp.async.wait_group 1;");
        }
        __syncthreads();          // stage 'stg' ready; everyone done with kt-1

        // prefetch tile kt+2 into pstg (= stage of kt-1, now free)
        if (kt + 2 < SS / 64) {
            __half* Kd = hsm + pstg * STAGEH;
            __half* Vd = Kd + TILEH;
            const __half* Kgs = Kg + (size_t)(kt + 2) * 64 * DD;
            const __half* Vgs = Vg + (size_t)(kt + 2) * 64 * DD;
#pragma unroll
            for (int i = 0; i < 4; i++) {
                int idx = t + 128 * i;
                int row = idx >> 3, c8 = (idx & 7) * 8;
                cp16h(&Kd[row * STRH + c8], Kgs + row * DD + c8);
                cp16h(&Vd[row * STRH + c8], Vgs + row * DD + c8);
            }
            asm volatile("cp.async.commit_group;");
        }

        const __half* Ks = hsm + stg * STAGEH;
        const __half* Vs = Ks + TILEH;

        // ---- GEMM1: S = Q @ K^T, fp16 acc; each B frag feeds 2 m-tiles ----
        uint32_t sh[2][8][2];
#pragma unroll
        for (int mi = 0; mi < 2; mi++)
#pragma unroll
            for (int nb = 0; nb < 8; nb++) { sh[mi][nb][0] = 0u; sh[mi][nb][1] = 0u; }

#pragma unroll
        for (int kb = 0; kb < 4; kb++) {
#pragma unroll
            for (int nb2 = 0; nb2 < 4; nb2++) {
                uint32_t br[4];
                ldsm4(br, &Ks[(nb2 * 16 + krow) * STRH + kb * 16 + kcol]);
#pragma unroll
                for (int mi = 0; mi < 2; mi++) {
                    mma_f16h(sh[mi][2 * nb2    ], qf[mi][kb], br[0], br[1]);
                    mma_f16h(sh[mi][2 * nb2 + 1], qf[mi][kb], br[2], br[3]);
                }
            }
        }

        // ---- P = exp2(S) IN PLACE (f16 D-frag == GEMM2 A-frag layout) ----
#pragma unroll
        for (int mi = 0; mi < 2; mi++)
#pragma unroll
            for (int nb = 0; nb < 8; nb++) {
                sh[mi][nb][0] = ex2h2(sh[mi][nb][0]);
                sh[mi][nb][1] = ex2h2(sh[mi][nb][1]);
            }

        // ---- GEMM2: O += P @ V (fp32 acc); row sums via ones-column block --
#pragma unroll
        for (int kb = 0; kb < 4; kb++) {
#pragma unroll
            for (int nb2 = 0; nb2 < 4; nb2++) {
                uint32_t bv[4];
                ldsm4t(bv, &Vs[(kb * 16 + vrow) * STRH + nb2 * 16 + vcol]);
#pragma unroll
                for (int mi = 0; mi < 2; mi++) {
                    uint32_t pa[4];
                    pa[0] = sh[mi][2 * kb    ][0];
                    pa[1] = sh[mi][2 * kb    ][1];
                    pa[2] = sh[mi][2 * kb + 1][0];
                    pa[3] = sh[mi][2 * kb + 1][1];
                    mma_f16(o[mi][2 * nb2    ], pa, bv[0], bv[1]);
                    mma_f16(o[mi][2 * nb2 + 1], pa, bv[2], bv[3]);
                }
            }
            uint32_t bs[2];
            ldsm2t(bs, &Vs[(kb * 16 + mb * 8 + lm2) * STRH + 64]);
#pragma unroll
            for (int mi = 0; mi < 2; mi++) {
                uint32_t pa[4];
                pa[0] = sh[mi][2 * kb    ][0];
                pa[1] = sh[mi][2 * kb    ][1];
                pa[2] = sh[mi][2 * kb + 1][0];
                pa[3] = sh[mi][2 * kb + 1][1];
                mma_f16(osum[mi], pa, bs[0], bs[1]);
            }
        }

        stg  = (stg  == 2) ? 0 : stg  + 1;
        pstg = (pstg == 2) ? 0 : pstg + 1;
    }

    // ---- epilogue: normalize, write fp16 [B,S,E] ----
    int b = bh >> 3, h = bh & 7;
#pragma unroll
    for (int mi = 0; mi < 2; mi++) {
        float l0 = __shfl_sync(0xffffffffu, osum[mi][0], 0, 4);
        float l1 = __shfl_sync(0xffffffffu, osum[mi][2], 0, 4);
        float inv0 = 1.f / l0, inv1 = 1.f / l1;
        int row0 = q0 + w * 32 + mi * 16 + r;
        __half* O0 = g_oh + ((size_t)(b * SS + row0    )) * EE + h * 64;
        __half* O1 = g_oh + ((size_t)(b * SS + row0 + 8)) * EE + h * 64;
#pragma unroll
        for (int nb = 0; nb < 8; nb++) {
            *(uint32_t*)(O0 + nb * 8 + 2 * c) =
                packh2(o[mi][nb][0] * inv0, o[mi][nb][1] * inv0);
            *(uint32_t*)(O1 + nb * 8 + 2 * c) =
                packh2(o[mi][nb][2] * inv1, o[mi][nb][3] * inv1);
        }
    }
}

// ---------------------------------------------------------------------------
// Kernel 3: output projection, fp16 mma, tile 128x128, 3-stage cp.async ring.
// ---------------------------------------------------------------------------
#define GSTR 72
#define GTILEH (128 * GSTR)
#define GSTAGEH (2 * GTILEH)                          // A tile + B tile
#define GSMEM (3 * GSTAGEH * (int)sizeof(__half))     // 110592 B

__global__ void __launch_bounds__(256) out_gemm_h(
    const float* __restrict__ bo, float* __restrict__ out)
{
    extern __shared__ __half gsm[];   // 3 stages x (A tile + B tile)

    int t  = threadIdx.x;
    int l  = t & 31;
    int w  = t >> 5;
    int r  = l >> 2;
    int c  = l & 3;
    int m  = l >> 3;
    int lm = l & 7;
    int arow = (m & 1) * 8 + lm, acol = (m >> 1) * 8;
    int brow = (m >> 1) * 8 + lm, bcol = (m & 1) * 8;
    int wm = (w & 3) * 32;
    int wn = (w >> 2) * 64;
    int m0 = blockIdx.x * 128;
    int n0 = blockIdx.y * 128;

    float acc[2][8][4];
#pragma unroll
    for (int mi = 0; mi < 2; mi++)
#pragma unroll
        for (int nb = 0; nb < 8; nb++)
#pragma unroll
            for (int j = 0; j < 4; j++) acc[mi][nb][j] = 0.f;

    // prologue: load k-chunks 0 and 1 into stages 0 and 1
#pragma unroll
    for (int pt = 0; pt < 2; pt++) {
        __half* As = gsm + pt * GSTAGEH;
        __half* Bs = As + GTILEH;
        int k0 = pt * 64;
#pragma unroll
        for (int i = 0; i < 4; i++) {
            int idx = t + 256 * i;
            int row = idx >> 3, c8 = (idx & 7) * 8;
            cp16h(&As[row * GSTR + c8], g_oh  + (size_t)(m0 + row) * 512 + k0 + c8);
            cp16h(&Bs[row * GSTR + c8], g_woh + (size_t)(n0 + row) * 512 + k0 + c8);
        }
        asm volatile("cp.async.commit_group;");
    }

    int stg = 0, pstg = 2;

    for (int kc = 0; kc < 8; kc++) {
        if (kc == 7) {
            asm volatile("cp.async.wait_group 0;");
        } else {
            asm volatile("cp.async.wait_group 1;");
        }
        __syncthreads();   // stage 'stg' ready; all warps done with kc-1

        // prefetch k-chunk kc+2 into pstg (stage consumed at kc-1, now free)
        if (kc + 2 < 8) {
            __half* Ad = gsm + pstg * GSTAGEH;
            __half* Bd = Ad + GTILEH;
            int k0 = (kc + 2) * 64;
#pragma unroll
            for (int i = 0; i < 4; i++) {
                int idx = t + 256 * i;
                int row = idx >> 3, c8 = (idx & 7) * 8;
                cp16h(&Ad[row * GSTR + c8], g_oh  + (size_t)(m0 + row) * 512 + k0 + c8);
                cp16h(&Bd[row * GSTR + c8], g_woh + (size_t)(n0 + row) * 512 + k0 + c8);
            }
            asm volatile("cp.async.commit_group;");
        }

        const __half* Asb = gsm + stg * GSTAGEH;
        const __half* Bsb = Asb + GTILEH;

#pragma unroll
        for (int k16 = 0; k16 < 4; k16++) {
            int kk = k16 * 16;
            uint32_t af[2][4];
            ldsm4(af[0], &Asb[(wm      + arow) * GSTR + kk + acol]);
            ldsm4(af[1], &Asb[(wm + 16 + arow) * GSTR + kk + acol]);
#pragma unroll
            for (int nb2 = 0; nb2 < 4; nb2++) {
                uint32_t bf[4];
                ldsm4(bf, &Bsb[(wn + nb2 * 16 + brow) * GSTR + kk + bcol]);
                mma_f16(acc[0][2 * nb2    ], af[0], bf[0], bf[1]);
                mma_f16(acc[0][2 * nb2 + 1], af[0], bf[2], bf[3]);
                mma_f16(acc[1][2 * nb2    ], af[1], bf[0], bf[1]);
                mma_f16(acc[1][2 * nb2 + 1], af[1], bf[2], bf[3]);
            }
        }

        stg  = (stg  == 2) ? 0 : stg  + 1;
        pstg = (pstg == 2) ? 0 : pstg + 1;
    }

#pragma unroll
    for (int mi = 0; mi < 2; mi++) {
        int row = m0 + wm + mi * 16 + r;
#pragma unroll
        for (int nb = 0; nb < 8; nb++) {
            int col = n0 + wn + nb * 8 + 2 * c;
            float b0 = bo[col], b1 = bo[col + 1];
            float2 lo; lo.x = acc[mi][nb][0] + b0; lo.y = acc[mi][nb][1] + b1;
            float2 hi; hi.x = acc[mi][nb][2] + b0; hi.y = acc[mi][nb][3] + b1;
            *(float2*)(out + (size_t)row * 512 + col)       = lo;
            *(float2*)(out + (size_t)(row + 8) * 512 + col) = hi;
        }
    }
}

// ---------------------------------------------------------------------------
// Launch.  Input order: values, keys, query, Wv, Wk, Wq, Wo, bo
// ---------------------------------------------------------------------------
extern "C" void kernel_launch(void* const* d_in, const int* in_sizes, int n_in,
                              void* d_out, int out_size)
{
    const float* values = (const float*)d_in[0];
    const float* keys   = (const float*)d_in[1];
    const float* query  = (const float*)d_in[2];
    const float* Wv     = (const float*)d_in[3];
    const float* Wk     = (const float*)d_in[4];
    const float* Wq     = (const float*)d_in[5];
    const float* Wo     = (const float*)d_in[6];
    const float* bo     = (const float*)d_in[7];
    float* out = (float*)d_out;

    static int configured = 0;
    if (!configured) {
        cudaFuncSetAttribute(flash11_kernel,
                             cudaFuncAttributeMaxDynamicSharedMemorySize, FSMEM);
        cudaFuncSetAttribute(out_gemm_h,
                             cudaFuncAttributeMaxDynamicSharedMemorySize, GSMEM);
        configured = 1;
    }

    dim3 pgrid(512, 4);
    proj_mma<<<pgrid, 256>>>(query, keys, values, Wq, Wk, Wv, Wo);

    dim3 fgrid(SS / 128, BB * HH);
    flash11_kernel<<<fgrid, 128, FSMEM>>>();

    dim3 ggrid((BB * SS) / 128, EE / 128);
    out_gemm_h<<<ggrid, 256, GSMEM>>>(bo, out);
}

// round 17
// speedup vs baseline: 1.0153x; 1.0153x over previous
#include <cuda_runtime.h>
#include <cuda_fp16.h>
#include <math.h>
#include <stdint.h>

#define BB 4
#define SS 2048
#define EE 512
#define HH 8
#define DD 64

#define STRH 72                 // flash SMEM tile row stride in halves
#define TILEH (64 * STRH)       // halves per 64x64 tile (pad cols 64..71)
#define STAGEH (2 * TILEH)      // K tile + V tile per pipeline stage
#define FSMEM (3 * STAGEH * (int)sizeof(__half))   // 55296 B

// softmax scale folded into Q: 1/sqrt(512) * log2(e)
#define CS 0.06376686479f

// Scratch (allocation-free requirement -> __device__ globals)
__device__ __half g_qh[BB * HH * SS * DD];  // [B,H,S,D] fp16, pre-scaled by CS
__device__ __half g_kh[BB * HH * SS * DD];  // [B,H,S,D] fp16
__device__ __half g_vh[BB * HH * SS * DD];  // [B,H,S,D] fp16
__device__ __half g_oh[BB * SS * EE];       // attention output [B,S,E] fp16
__device__ __half g_woh[EE * EE];           // Wo in fp16

// ---------------------------------------------------------------------------
// helpers
// ---------------------------------------------------------------------------
__device__ __forceinline__ uint32_t packh2(float lo, float hi) {
    uint32_t d;
    asm("cvt.rn.f16x2.f32 %0, %1, %2;" : "=r"(d) : "f"(hi), "f"(lo));
    return d;
}

__device__ __forceinline__ uint32_t ex2h2(uint32_t a) {
    uint32_t d;
    asm("ex2.approx.f16x2 %0, %1;" : "=r"(d) : "r"(a));
    return d;
}

__device__ __forceinline__ void mma_f16(float d[4], const uint32_t a[4],
                                        uint32_t b0, uint32_t b1) {
    asm volatile(
        "mma.sync.aligned.m16n8k16.row.col.f32.f16.f16.f32 "
        "{%0,%1,%2,%3}, {%4,%5,%6,%7}, {%8,%9}, {%0,%1,%2,%3};"
        : "+f"(d[0]), "+f"(d[1]), "+f"(d[2]), "+f"(d[3])
        : "r"(a[0]), "r"(a[1]), "r"(a[2]), "r"(a[3]), "r"(b0), "r"(b1));
}

// fp16-accumulate variant: D/C are 2 packed f16x2 regs (2x HMMA rate)
__device__ __forceinline__ void mma_f16h(uint32_t d[2], const uint32_t a[4],
                                         uint32_t b0, uint32_t b1) {
    asm volatile(
        "mma.sync.aligned.m16n8k16.row.col.f16.f16.f16.f16 "
        "{%0,%1}, {%2,%3,%4,%5}, {%6,%7}, {%0,%1};"
        : "+r"(d[0]), "+r"(d[1])
        : "r"(a[0]), "r"(a[1]), "r"(a[2]), "r"(a[3]), "r"(b0), "r"(b1));
}

__device__ __forceinline__ void ldsm4(uint32_t r[4], const __half* p) {
    uint32_t a = (uint32_t)__cvta_generic_to_shared(p);
    asm volatile("ldmatrix.sync.aligned.m8n8.x4.shared.b16 {%0,%1,%2,%3}, [%4];"
                 : "=r"(r[0]), "=r"(r[1]), "=r"(r[2]), "=r"(r[3]) : "r"(a));
}

__device__ __forceinline__ void ldsm4t(uint32_t r[4], const __half* p) {
    uint32_t a = (uint32_t)__cvta_generic_to_shared(p);
    asm volatile("ldmatrix.sync.aligned.m8n8.x4.trans.shared.b16 {%0,%1,%2,%3}, [%4];"
                 : "=r"(r[0]), "=r"(r[1]), "=r"(r[2]), "=r"(r[3]) : "r"(a));
}

__device__ __forceinline__ void ldsm2t(uint32_t r[2], const __half* p) {
    uint32_t a = (uint32_t)__cvta_generic_to_shared(p);
    asm volatile("ldmatrix.sync.aligned.m8n8.x2.trans.shared.b16 {%0,%1}, [%2];"
                 : "=r"(r[0]), "=r"(r[1]) : "r"(a));
}

__device__ __forceinline__ void cp16h(__half* smem_dst, const __half* gsrc) {
    uint32_t s = (uint32_t)__cvta_generic_to_shared(smem_dst);
    asm volatile("cp.async.cg.shared.global [%0], [%1], 16;" :: "r"(s), "l"(gsrc));
}

// ---------------------------------------------------------------------------
// Kernel 1: fused per-head projections on fp16 tensor cores + Wo convert.
// grid (256, 4); blockIdx.y: 0=Q, 1=K, 2=V, 3=Wo fp32->fp16.
// 8 warps, warp M-tile 32 (256 rows/CTA): W-tile ldsm + LDG amortized 2x.
// ---------------------------------------------------------------------------
#define PXSTR 72

__global__ void __launch_bounds__(256) proj_mma(
    const float* __restrict__ q, const float* __restrict__ k,
    const float* __restrict__ v,
    const float* __restrict__ Wq, const float* __restrict__ Wk,
    const float* __restrict__ Wv, const float* __restrict__ Wo)
{
    int which = blockIdx.y;
    if (which == 3) {
        // Wo convert: 256 blocks x 256 threads x 4 floats = 262144
        int i = (blockIdx.x * 256 + threadIdx.x) * 4;
        float4 f = *(const float4*)(Wo + i);
        *(uint32_t*)(g_woh + i)     = packh2(f.x, f.y);
        *(uint32_t*)(g_woh + i + 2) = packh2(f.z, f.w);
        return;
    }

    const float* x = (which == 0) ? q : (which == 1) ? k : v;
    const float* W = (which == 0) ? Wq : (which == 1) ? Wk : Wv;
    __half* outh   = (which == 0) ? g_qh : (which == 1) ? g_kh : g_vh;
    float scale    = (which == 0) ? CS : 1.0f;

    __shared__ __half Xs[256 * PXSTR];   // also reused as epilogue buffer
    __shared__ __half Ws[64 * PXSTR];

    int t  = threadIdx.x;
    int l  = t & 31;
    int w  = t >> 5;                     // 0..7, warp owns rows w*32..w*32+31
    int r  = l >> 2;
    int c  = l & 3;
    int m  = l >> 3;
    int lm = l & 7;
    int arow = (m & 1) * 8 + lm, acol = (m >> 1) * 8;
    int brow = (m >> 1) * 8 + lm, bcol = (m & 1) * 8;

    int rbase = blockIdx.x * 256;

    // ---- W (64x64 fp32) -> fp16 SMEM, 128-bit STS ----
    {
        int row = t >> 2, c16 = (t & 3) * 16;
        const float* wp = W + row * 64 + c16;
        float4 f0 = *(const float4*)(wp);
        float4 f1 = *(const float4*)(wp + 4);
        float4 f2 = *(const float4*)(wp + 8);
        float4 f3 = *(const float4*)(wp + 12);
        uint4 u0, u1;
        u0.x = packh2(f0.x, f0.y); u0.y = packh2(f0.z, f0.w);
        u0.z = packh2(f1.x, f1.y); u0.w = packh2(f1.z, f1.w);
        u1.x = packh2(f2.x, f2.y); u1.y = packh2(f2.z, f2.w);
        u1.z = packh2(f3.x, f3.y); u1.w = packh2(f3.z, f3.w);
        *(uint4*)(&Ws[row * PXSTR + c16])     = u0;
        *(uint4*)(&Ws[row * PXSTR + c16 + 8]) = u1;
    }
    // ---- X tile (256x64 fp32) -> fp16 SMEM, 128-bit STS ----
    {
#pragma unroll
        for (int i = 0; i < 4; i++) {
            int idx = t + 256 * i;              // 0..1023
            int row = idx >> 2, c16 = (idx & 3) * 16;
            const float* xp = x + (size_t)(rbase + row) * 64 + c16;
            float4 f0 = *(const float4*)(xp);
            float4 f1 = *(const float4*)(xp + 4);
            float4 f2 = *(const float4*)(xp + 8);
            float4 f3 = *(const float4*)(xp + 12);
            uint4 u0, u1;
            u0.x = packh2(f0.x, f0.y); u0.y = packh2(f0.z, f0.w);
            u0.z = packh2(f1.x, f1.y); u0.w = packh2(f1.z, f1.w);
            u1.x = packh2(f2.x, f2.y); u1.y = packh2(f2.z, f2.w);
            u1.z = packh2(f3.x, f3.y); u1.w = packh2(f3.z, f3.w);
            *(uint4*)(&Xs[row * PXSTR + c16])     = u0;
            *(uint4*)(&Xs[row * PXSTR + c16 + 8]) = u1;
        }
    }
    __syncthreads();

    // ---- warp GEMM: 32 rows x 64 e, K = 64; B frags shared by 2 m-tiles ----
    float acc[2][8][4];
#pragma unroll
    for (int mi = 0; mi < 2; mi++)
#pragma unroll
        for (int nb = 0; nb < 8; nb++)
#pragma unroll
            for (int j = 0; j < 4; j++) acc[mi][nb][j] = 0.f;

#pragma unroll
    for (int k16 = 0; k16 < 4; k16++) {
        int kk = k16 * 16;
        uint32_t af[2][4];
        ldsm4(af[0], &Xs[(w * 32      + arow) * PXSTR + kk + acol]);
        ldsm4(af[1], &Xs[(w * 32 + 16 + arow) * PXSTR + kk + acol]);
#pragma unroll
        for (int nb2 = 0; nb2 < 4; nb2++) {
            uint32_t bf[4];
            ldsm4(bf, &Ws[(nb2 * 16 + brow) * PXSTR + kk + bcol]);
            mma_f16(acc[0][2 * nb2    ], af[0], bf[0], bf[1]);
            mma_f16(acc[0][2 * nb2 + 1], af[0], bf[2], bf[3]);
            mma_f16(acc[1][2 * nb2    ], af[1], bf[0], bf[1]);
            mma_f16(acc[1][2 * nb2 + 1], af[1], bf[2], bf[3]);
        }
    }

    // ---- epilogue: fragments -> SMEM (reuse Xs), then coalesced STG.128 ----
    __syncthreads();   // all ldsm reads of Xs done
    __half* Es = Xs;
#pragma unroll
    for (int mi = 0; mi < 2; mi++) {
#pragma unroll
        for (int half = 0; half < 2; half++) {
            int row = w * 32 + mi * 16 + r + 8 * half;
#pragma unroll
            for (int nb = 0; nb < 8; nb++) {
                *(uint32_t*)(&Es[row * PXSTR + nb * 8 + 2 * c]) =
                    packh2(acc[mi][nb][2 * half    ] * scale,
                           acc[mi][nb][2 * half + 1] * scale);
            }
        }
    }
    __syncthreads();

#pragma unroll
    for (int i = t; i < 2048; i += 256) {
        int row = i >> 3, seg = i & 7;
        int n   = rbase + row;
        int b   = n >> 14;
        int rem = n & 16383;
        int s   = rem >> 3;
        int h   = rem & 7;
        __half* Ob = outh + (((size_t)(b * HH + h) * SS) + s) * 64;
        *(uint4*)(Ob + seg * 8) = *(const uint4*)(&Es[row * PXSTR + seg * 8]);
    }
}

// ---------------------------------------------------------------------------
// Kernel 2: flash attention (round-15 champion, unchanged).
// fp16-acc GEMM1, fp32-acc GEMM2, ones-column row sums, warp M-tile 32,
// 4 warps/CTA, q-block 128, Bc = 64, 3-stage cp.async ring, 1 barrier/tile.
// ---------------------------------------------------------------------------
__global__ void __launch_bounds__(128, 2) flash9_kernel()
{
    extern __shared__ __half hsm[];   // 3 stages x (K tile + V tile)

    int t  = threadIdx.x;
    int l  = t & 31;
    int w  = t >> 5;                // 0..3, warp owns rows w*32..w*32+31
    int bh = blockIdx.y;
    int q0 = blockIdx.x * 128;
    int r  = l >> 2;
    int c  = l & 3;
    int m  = l >> 3;
    int lm = l & 7;

    int krow = (m >> 1) * 8 + lm;   // K ldsm (non-trans)
    int kcol = (m & 1) * 8;
    int vrow = (m & 1) * 8 + lm;    // V ldsm (trans)
    int vcol = (m >> 1) * 8;
    int lm2  = l & 7;               // ldsm2t lanes
    int mb   = (l >> 3) & 1;

    const __half* Kg = g_kh + (size_t)bh * SS * DD;
    const __half* Vg = g_vh + (size_t)bh * SS * DD;

    // ---- V pad columns: [1,0,...,0] per row, all 3 stages (written once) ----
    for (int i = t; i < 192; i += 128) {
        int stg = i >> 6, row = i & 63;
        uint4 z; z.x = 0x00003C00u; z.y = 0; z.z = 0; z.w = 0;
        *(uint4*)(hsm + stg * STAGEH + TILEH + row * STRH + 64) = z;
    }

    // ---- Q a-fragments: 2 m16 sub-tiles (rows w*32 and w*32+16) ----
    uint32_t qf[2][4][4];
    {
        const __half* Qb = g_qh + ((size_t)bh * SS + q0 + w * 32) * DD;
#pragma unroll
        for (int mi = 0; mi < 2; mi++)
#pragma unroll
            for (int kb = 0; kb < 4; kb++) {
                const __half* Qm = Qb + (size_t)mi * 16 * 64;
                qf[mi][kb][0] = *(const uint32_t*)(Qm + (r    ) * 64 + kb * 16 + 2 * c    );
                qf[mi][kb][1] = *(const uint32_t*)(Qm + (r + 8) * 64 + kb * 16 + 2 * c    );
                qf[mi][kb][2] = *(const uint32_t*)(Qm + (r    ) * 64 + kb * 16 + 2 * c + 8);
                qf[mi][kb][3] = *(const uint32_t*)(Qm + (r + 8) * 64 + kb * 16 + 2 * c + 8);
            }
    }

    float o[2][8][4];
#pragma unroll
    for (int mi = 0; mi < 2; mi++)
#pragma unroll
        for (int nb = 0; nb < 8; nb++)
#pragma unroll
            for (int j = 0; j < 4; j++) o[mi][nb][j] = 0.f;
    float osum[2][4] = {{0.f, 0.f, 0.f, 0.f}, {0.f, 0.f, 0.f, 0.f}};

    // prologue: load tiles 0 and 1 into stages 0 and 1
#pragma unroll
    for (int pt = 0; pt < 2; pt++) {
        __half* Kd = hsm + pt * STAGEH;
        __half* Vd = Kd + TILEH;
        const __half* Kgs = Kg + (size_t)pt * 64 * DD;
        const __half* Vgs = Vg + (size_t)pt * 64 * DD;
#pragma unroll
        for (int i = 0; i < 4; i++) {
            int idx = t + 128 * i;          // 0..511
            int row = idx >> 3, c8 = (idx & 7) * 8;
            cp16h(&Kd[row * STRH + c8], Kgs + row * DD + c8);
            cp16h(&Vd[row * STRH + c8], Vgs + row * DD + c8);
        }
        asm volatile("cp.async.commit_group;");
    }

    int stg = 0;                  // stage of tile kt
    int pstg = 2;                 // stage receiving tile kt+2

    for (int kt = 0; kt < SS / 64; kt++) {
        if (kt == SS / 64 - 1) {
            asm volatile("cp.async.wait_group 0;");
        } else {
            asm volatile("cp.async.wait_group 1;");
        }
        __syncthreads();          // stage 'stg' ready; everyone done with kt-1

        // prefetch tile kt+2 into pstg (= stage of kt-1, now free)
        if (kt + 2 < SS / 64) {
            __half* Kd = hsm + pstg * STAGEH;
            __half* Vd = Kd + TILEH;
            const __half* Kgs = Kg + (size_t)(kt + 2) * 64 * DD;
            const __half* Vgs = Vg + (size_t)(kt + 2) * 64 * DD;
#pragma unroll
            for (int i = 0; i < 4; i++) {
                int idx = t + 128 * i;
                int row = idx >> 3, c8 = (idx & 7) * 8;
                cp16h(&Kd[row * STRH + c8], Kgs + row * DD + c8);
                cp16h(&Vd[row * STRH + c8], Vgs + row * DD + c8);
            }
            asm volatile("cp.async.commit_group;");
        }

        const __half* Ks = hsm + stg * STAGEH;
        const __half* Vs = Ks + TILEH;

        // ---- GEMM1: S = Q @ K^T, fp16 acc; each B frag feeds 2 m-tiles ----
        uint32_t sh[2][8][2];
#pragma unroll
        for (int mi = 0; mi < 2; mi++)
#pragma unroll
            for (int nb = 0; nb < 8; nb++) { sh[mi][nb][0] = 0u; sh[mi][nb][1] = 0u; }

#pragma unroll
        for (int kb = 0; kb < 4; kb++) {
#pragma unroll
            for (int nb2 = 0; nb2 < 4; nb2++) {
                uint32_t br[4];
                ldsm4(br, &Ks[(nb2 * 16 + krow) * STRH + kb * 16 + kcol]);
#pragma unroll
                for (int mi = 0; mi < 2; mi++) {
                    mma_f16h(sh[mi][2 * nb2    ], qf[mi][kb], br[0], br[1]);
                    mma_f16h(sh[mi][2 * nb2 + 1], qf[mi][kb], br[2], br[3]);
                }
            }
        }

        // ---- P = exp2(S): f16 D-frag already in GEMM2 A-frag layout ----
        uint32_t pa[2][4][4];
#pragma unroll
        for (int mi = 0; mi < 2; mi++)
#pragma unroll
            for (int kb = 0; kb < 4; kb++) {
                pa[mi][kb][0] = ex2h2(sh[mi][2 * kb    ][0]);
                pa[mi][kb][1] = ex2h2(sh[mi][2 * kb    ][1]);
                pa[mi][kb][2] = ex2h2(sh[mi][2 * kb + 1][0]);
                pa[mi][kb][3] = ex2h2(sh[mi][2 * kb + 1][1]);
            }

        // ---- GEMM2: O += P @ V (fp32 acc); row sums via ones-column block --
#pragma unroll
        for (int kb = 0; kb < 4; kb++) {
#pragma unroll
            for (int nb2 = 0; nb2 < 4; nb2++) {
                uint32_t bv[4];
                ldsm4t(bv, &Vs[(kb * 16 + vrow) * STRH + nb2 * 16 + vcol]);
#pragma unroll
                for (int mi = 0; mi < 2; mi++) {
                    mma_f16(o[mi][2 * nb2    ], pa[mi][kb], bv[0], bv[1]);
                    mma_f16(o[mi][2 * nb2 + 1], pa[mi][kb], bv[2], bv[3]);
                }
            }
            uint32_t bs[2];
            ldsm2t(bs, &Vs[(kb * 16 + mb * 8 + lm2) * STRH + 64]);
            mma_f16(osum[0], pa[0][kb], bs[0], bs[1]);
            mma_f16(osum[1], pa[1][kb], bs[0], bs[1]);
        }

        stg  = (stg  == 2) ? 0 : stg  + 1;
        pstg = (pstg == 2) ? 0 : pstg + 1;
    }

    // ---- epilogue: normalize, write fp16 [B,S,E] ----
    int b = bh >> 3, h = bh & 7;
#pragma unroll
    for (int mi = 0; mi < 2; mi++) {
        float l0 = __shfl_sync(0xffffffffu, osum[mi][0], 0, 4);
        float l1 = __shfl_sync(0xffffffffu, osum[mi][2], 0, 4);
        float inv0 = 1.f / l0, inv1 = 1.f / l1;
        int row0 = q0 + w * 32 + mi * 16 + r;
        __half* O0 = g_oh + ((size_t)(b * SS + row0    )) * EE + h * 64;
        __half* O1 = g_oh + ((size_t)(b * SS + row0 + 8)) * EE + h * 64;
#pragma unroll
        for (int nb = 0; nb < 8; nb++) {
            *(uint32_t*)(O0 + nb * 8 + 2 * c) =
                packh2(o[mi][nb][0] * inv0, o[mi][nb][1] * inv0);
            *(uint32_t*)(O1 + nb * 8 + 2 * c) =
                packh2(o[mi][nb][2] * inv1, o[mi][nb][3] * inv1);
        }
    }
}

// ---------------------------------------------------------------------------
// Kernel 3: output projection, fp16 mma, tile 128x128, 3-stage cp.async ring.
// ---------------------------------------------------------------------------
#define GSTR 72
#define GTILEH (128 * GSTR)
#define GSTAGEH (2 * GTILEH)                          // A tile + B tile
#define GSMEM (3 * GSTAGEH * (int)sizeof(__half))     // 110592 B

__global__ void __launch_bounds__(256) out_gemm_h(
    const float* __restrict__ bo, float* __restrict__ out)
{
    extern __shared__ __half gsm[];   // 3 stages x (A tile + B tile)

    int t  = threadIdx.x;
    int l  = t & 31;
    int w  = t >> 5;
    int r  = l >> 2;
    int c  = l & 3;
    int m  = l >> 3;
    int lm = l & 7;
    int arow = (m & 1) * 8 + lm, acol = (m >> 1) * 8;
    int brow = (m >> 1) * 8 + lm, bcol = (m & 1) * 8;
    int wm = (w & 3) * 32;
    int wn = (w >> 2) * 64;
    int m0 = blockIdx.x * 128;
    int n0 = blockIdx.y * 128;

    float acc[2][8][4];
#pragma unroll
    for (int mi = 0; mi < 2; mi++)
#pragma unroll
        for (int nb = 0; nb < 8; nb++)
#pragma unroll
            for (int j = 0; j < 4; j++) acc[mi][nb][j] = 0.f;

    // prologue: load k-chunks 0 and 1 into stages 0 and 1
#pragma unroll
    for (int pt = 0; pt < 2; pt++) {
        __half* As = gsm + pt * GSTAGEH;
        __half* Bs = As + GTILEH;
        int k0 = pt * 64;
#pragma unroll
        for (int i = 0; i < 4; i++) {
            int idx = t + 256 * i;
            int row = idx >> 3, c8 = (idx & 7) * 8;
            cp16h(&As[row * GSTR + c8], g_oh  + (size_t)(m0 + row) * 512 + k0 + c8);
            cp16h(&Bs[row * GSTR + c8], g_woh + (size_t)(n0 + row) * 512 + k0 + c8);
        }
        asm volatile("cp.async.commit_group;");
    }

    int stg = 0, pstg = 2;

    for (int kc = 0; kc < 8; kc++) {
        if (kc == 7) {
            asm volatile("cp.async.wait_group 0;");
        } else {
            asm volatile("cp.async.wait_group 1;");
        }
        __syncthreads();   // stage 'stg' ready; all warps done with kc-1

        // prefetch k-chunk kc+2 into pstg (stage consumed at kc-1, now free)
        if (kc + 2 < 8) {
            __half* Ad = gsm + pstg * GSTAGEH;
            __half* Bd = Ad + GTILEH;
            int k0 = (kc + 2) * 64;
#pragma unroll
            for (int i = 0; i < 4; i++) {
                int idx = t + 256 * i;
                int row = idx >> 3, c8 = (idx & 7) * 8;
                cp16h(&Ad[row * GSTR + c8], g_oh  + (size_t)(m0 + row) * 512 + k0 + c8);
                cp16h(&Bd[row * GSTR + c8], g_woh + (size_t)(n0 + row) * 512 + k0 + c8);
            }
            asm volatile("cp.async.commit_group;");
        }

        const __half* Asb = gsm + stg * GSTAGEH;
        const __half* Bsb = Asb + GTILEH;

#pragma unroll
        for (int k16 = 0; k16 < 4; k16++) {
            int kk = k16 * 16;
            uint32_t af[2][4];
            ldsm4(af[0], &Asb[(wm      + arow) * GSTR + kk + acol]);
            ldsm4(af[1], &Asb[(wm + 16 + arow) * GSTR + kk + acol]);
#pragma unroll
            for (int nb2 = 0; nb2 < 4; nb2++) {
                uint32_t bf[4];
                ldsm4(bf, &Bsb[(wn + nb2 * 16 + brow) * GSTR + kk + bcol]);
                mma_f16(acc[0][2 * nb2    ], af[0], bf[0], bf[1]);
                mma_f16(acc[0][2 * nb2 + 1], af[0], bf[2], bf[3]);
                mma_f16(acc[1][2 * nb2    ], af[1], bf[0], bf[1]);
                mma_f16(acc[1][2 * nb2 + 1], af[1], bf[2], bf[3]);
            }
        }

        stg  = (stg  == 2) ? 0 : stg  + 1;
        pstg = (pstg == 2) ? 0 : pstg + 1;
    }

#pragma unroll
    for (int mi = 0; mi < 2; mi++) {
        int row = m0 + wm + mi * 16 + r;
#pragma unroll
        for (int nb = 0; nb < 8; nb++) {
            int col = n0 + wn + nb * 8 + 2 * c;
            float b0 = bo[col], b1 = bo[col + 1];
            float2 lo; lo.x = acc[mi][nb][0] + b0; lo.y = acc[mi][nb][1] + b1;
            float2 hi; hi.x = acc[mi][nb][2] + b0; hi.y = acc[mi][nb][3] + b1;
            *(float2*)(out + (size_t)row * 512 + col)       = lo;
            *(float2*)(out + (size_t)(row + 8) * 512 + col) = hi;
        }
    }
}

// ---------------------------------------------------------------------------
// Launch.  Input order: values, keys, query, Wv, Wk, Wq, Wo, bo
// ---------------------------------------------------------------------------
extern "C" void kernel_launch(void* const* d_in, const int* in_sizes, int n_in,
                              void* d_out, int out_size)
{
    const float* values = (const float*)d_in[0];
    const float* keys   = (const float*)d_in[1];
    const float* query  = (const float*)d_in[2];
    const float* Wv     = (const float*)d_in[3];
    const float* Wk     = (const float*)d_in[4];
    const float* Wq     = (const float*)d_in[5];
    const float* Wo     = (const float*)d_in[6];
    const float* bo     = (const float*)d_in[7];
    float* out = (float*)d_out;

    static int configured = 0;
    if (!configured) {
        cudaFuncSetAttribute(flash9_kernel,
                             cudaFuncAttributeMaxDynamicSharedMemorySize, FSMEM);
        cudaFuncSetAttribute(out_gemm_h,
                             cudaFuncAttributeMaxDynamicSharedMemorySize, GSMEM);
        configured = 1;
    }

    dim3 pgrid(256, 4);
    proj_mma<<<pgrid, 256>>>(query, keys, values, Wq, Wk, Wv, Wo);

    dim3 fgrid(SS / 128, BB * HH);
    flash9_kernel<<<fgrid, 128, FSMEM>>>();

    dim3 ggrid((BB * SS) / 128, EE / 128);
    out_gemm_h<<<ggrid, 256, GSMEM>>>(bo, out);
}